// round 14
// baseline (speedup 1.0000x reference)
#include <cuda_runtime.h>
#include <cuda_fp16.h>
#include <math.h>
#include <stdint.h>

#define EMBED 512
#define HEADS 8
#define HDIM 64
#define SEQL 65
#define NPATCH 64
#define PFEAT 48
#define HID 1024
#define NCLS 10
#define BATCH 2048
#define MTOT (BATCH * SEQL)     // 133120
#define MP (BATCH * NPATCH)     // 131072 (patch GEMM rows)

// global scratch (no allocations allowed)
__device__ __align__(16) __half g_p16[(size_t)MP * 64];
__device__ __align__(16) __half g_pw16[EMBED * 64];
__device__ __align__(16) __half g_s16[(size_t)MTOT * EMBED];
__device__ __align__(16) __half g_wq16[EMBED * EMBED];
__device__ __align__(16) __half g_wo16[EMBED * EMBED];
__device__ __align__(16) __half g_w116[HID * EMBED];
__device__ __align__(16) __half g_q16[(size_t)MTOT * EMBED];
__device__ __align__(16) __half g_cp16[BATCH * EMBED];
__device__ __align__(16) __half g_ct16[BATCH * EMBED];
__device__ __align__(16) float g_h[BATCH * HID];

// ---------------- helpers ----------------
// exp via MUFU ex2 (offloads the fma pipe; ~2^-22 rel err)
__device__ __forceinline__ float fexp(float x) {
    float y = x * 1.4426950408889634f;
    float r;
    asm("ex2.approx.f32 %0, %1;" : "=f"(r) : "f"(y));
    return r;
}
// fp16 x fp16 -> fp32 accum MMA
__device__ __forceinline__ void mma16816h(float* c, const uint32_t* a,
                                          const uint32_t* b) {
    asm volatile(
        "mma.sync.aligned.m16n8k16.row.col.f32.f16.f16.f32 "
        "{%0,%1,%2,%3}, {%4,%5,%6,%7}, {%8,%9}, {%0,%1,%2,%3};"
        : "+f"(c[0]), "+f"(c[1]), "+f"(c[2]), "+f"(c[3])
        : "r"(a[0]), "r"(a[1]), "r"(a[2]), "r"(a[3]), "r"(b[0]), "r"(b[1]));
}
__device__ __forceinline__ void ldsm4(uint32_t* r, uint32_t addr) {
    asm volatile("ldmatrix.sync.aligned.m8n8.x4.shared.b16 {%0,%1,%2,%3}, [%4];"
                 : "=r"(r[0]), "=r"(r[1]), "=r"(r[2]), "=r"(r[3]) : "r"(addr));
}
__device__ __forceinline__ void cp16(uint32_t dst_smem, const void* src) {
    asm volatile("cp.async.ca.shared.global [%0], [%1], 16;"
                 :: "r"(dst_smem), "l"(src));
}
__device__ __forceinline__ void cpcommit() { asm volatile("cp.async.commit_group;"); }
__device__ __forceinline__ void cpwait0()  { asm volatile("cp.async.wait_group 0;"); }

// ---------------------------------------------------------------------------
// K1 "prep": fused patchify (p16, zero-padded K=64) + seq row0 + all weight
// conversions to fp16. Block ranges select the job.
// ---------------------------------------------------------------------------
#define PREP_PATCH 2048
#define PREP_PW    128
#define PREP_WQ    1024
#define PREP_WO    1024
#define PREP_W1    2048
#define PREP_GRID (PREP_PATCH + PREP_PW + PREP_WQ + PREP_WO + PREP_W1)

__global__ __launch_bounds__(256) void prep_kernel(
    const float* __restrict__ x, const float* __restrict__ proj_w,
    const float* __restrict__ cls, const float* __restrict__ pos,
    const float* __restrict__ wq, const float* __restrict__ wo,
    const float* __restrict__ w1,
    __half* __restrict__ p16, __half* __restrict__ pw16,
    __half* __restrict__ s16, __half* __restrict__ wq16,
    __half* __restrict__ wo16, __half* __restrict__ w116)
{
    const int bid = blockIdx.x, t = threadIdx.x;
    if (bid < PREP_PATCH) {
        const int b = bid;
        const float* xb = x + (size_t)b * 3 * 32 * 32;
        __half* pb = p16 + (size_t)b * NPATCH * 64;
        for (int idx = t; idx < NPATCH * PFEAT; idx += 256) {
            int n = idx / PFEAT, f = idx % PFEAT;
            int c = f >> 4, r4 = (f >> 2) & 3, c4 = f & 3;
            int py = n >> 3, px = n & 7;
            pb[n * 64 + f] = __float2half(xb[c * 1024 + (py * 4 + r4) * 32 + (px * 4 + c4)]);
        }
        for (int idx = t; idx < NPATCH * 16; idx += 256) {
            int n = idx >> 4, f = 48 + (idx & 15);
            pb[n * 64 + f] = __float2half(0.f);
        }
        for (int e = t; e < EMBED; e += 256)
            s16[(size_t)b * SEQL * EMBED + e] = __float2half(cls[e] + pos[e]);
        return;
    }
    int r = bid - PREP_PATCH;
    if (r < PREP_PW) {
        int idx = r * 256 + t;
        int row = idx >> 6, col = idx & 63;
        pw16[idx] = __float2half(col < PFEAT ? proj_w[row * PFEAT + col] : 0.f);
        return;
    }
    r -= PREP_PW;
    if (r < PREP_WQ) { int i = r * 256 + t; wq16[i] = __float2half(wq[i]); return; }
    r -= PREP_WQ;
    if (r < PREP_WO) { int i = r * 256 + t; wo16[i] = __float2half(wo[i]); return; }
    r -= PREP_WO;
    { int i = r * 256 + t; w116[i] = __float2half(w1[i]); }
}

// ---------------------------------------------------------------------------
// K2: fp16 MMA GEMM, K-chunk 64, double buffer, ONE barrier per chunk.
// CTA 128x128, 8 warps (4m x 2n), warp tile 32x64.
// mode 0: fp16 out; mode 1: fp32 + exact GELU; mode 2: fp16 out with
// row remap m -> (m/64)*65+1+(m%64) and += pos[(1+m%64)*EMBED + n].
// ---------------------------------------------------------------------------
#define QSTR 72
#define KC 64

__global__ __launch_bounds__(256, 2) void mma_gemm_kernel(
    const __half* __restrict__ A, int ldA,
    const __half* __restrict__ W, int ldW,
    const float* __restrict__ bias, const float* __restrict__ pos,
    __half* __restrict__ Ch, float* __restrict__ Cf,
    int ldC, int nchk, int mode)
{
    __shared__ __align__(16) __half sA[2][128 * QSTR];
    __shared__ __align__(16) __half sW[2][128 * QSTR];

    const int t = threadIdx.x;
    const int wid = t >> 5, lane = t & 31;
    const int gid = lane >> 2, tig = lane & 3;
    const int wm = wid & 3, wn = wid >> 2;
    const int m0 = blockIdx.y * 128, n0 = blockIdx.x * 128;

    float acc[2][8][4];
    #pragma unroll
    for (int i = 0; i < 2; i++)
        #pragma unroll
        for (int j = 0; j < 8; j++)
            #pragma unroll
            for (int k = 0; k < 4; k++) acc[i][j][k] = 0.f;

    const uint32_t stg = 128 * QSTR * 2;
    const uint32_t baseA = (uint32_t)__cvta_generic_to_shared(&sA[0][0]);
    const uint32_t baseW = (uint32_t)__cvta_generic_to_shared(&sW[0][0]);

    const int crow = t >> 3, ccol = (t & 7) * 8;
    auto issue = [&](int c, int s) {
        const uint32_t so = s * stg;
        const size_t ko = (size_t)c * KC + ccol;
        #pragma unroll
        for (int j = 0; j < 4; j++) {
            int row = crow + j * 32;
            uint32_t d = (uint32_t)((row * QSTR + ccol) * 2);
            cp16(baseA + so + d, A + (size_t)(m0 + row) * ldA + ko);
            cp16(baseW + so + d, W + (size_t)(n0 + row) * ldW + ko);
        }
        cpcommit();
    };

    const int aoff = (wm * 32 + (lane & 15)) * QSTR + (lane >> 4) * 8;
    const int boffn = wn * 64 + ((lane >> 4) << 3) + (lane & 7);
    const int boffk = ((lane >> 3) & 1) * 8;

    issue(0, 0);
    for (int c = 0; c < nchk; c++) {
        const int s = c & 1;
        cpwait0();
        __syncthreads();
        if (c + 1 < nchk) issue(c + 1, s ^ 1);
        const uint32_t so = s * stg;
        #pragma unroll
        for (int ks = 0; ks < 4; ks++) {
            const int k0 = ks * 16;
            uint32_t ah[2][4];
            #pragma unroll
            for (int mt = 0; mt < 2; mt++)
                ldsm4(ah[mt], baseA + so + (uint32_t)((aoff + mt * 16 * QSTR + k0) * 2));
            #pragma unroll
            for (int p = 0; p < 4; p++) {
                uint32_t bb[4];
                ldsm4(bb, baseW + so + (uint32_t)(((boffn + p * 16) * QSTR + k0 + boffk) * 2));
                #pragma unroll
                for (int mt = 0; mt < 2; mt++) {
                    mma16816h(acc[mt][2 * p],     ah[mt], bb);
                    mma16816h(acc[mt][2 * p + 1], ah[mt], bb + 2);
                }
            }
        }
    }

    __syncthreads();
    #pragma unroll
    for (int mt = 0; mt < 2; mt++) {
        int m1 = m0 + wm * 32 + mt * 16 + gid;   // rows m1, m1+8
        #pragma unroll
        for (int nt = 0; nt < 8; nt++) {
            int n = n0 + wn * 64 + nt * 8 + tig * 2;
            float b0 = bias[n], b1 = bias[n + 1];
            float v00 = acc[mt][nt][0] + b0, v01 = acc[mt][nt][1] + b1;
            float v10 = acc[mt][nt][2] + b0, v11 = acc[mt][nt][3] + b1;
            if (mode == 0) {
                __half2 H0; H0.x = __float2half(v00); H0.y = __float2half(v01);
                __half2 H1; H1.x = __float2half(v10); H1.y = __float2half(v11);
                *(__half2*)(Ch + (size_t)m1 * ldC + n)       = H0;
                *(__half2*)(Ch + (size_t)(m1 + 8) * ldC + n) = H1;
            } else if (mode == 1) {
                v00 = 0.5f * v00 * (1.f + erff(v00 * 0.70710678118654752f));
                v01 = 0.5f * v01 * (1.f + erff(v01 * 0.70710678118654752f));
                v10 = 0.5f * v10 * (1.f + erff(v10 * 0.70710678118654752f));
                v11 = 0.5f * v11 * (1.f + erff(v11 * 0.70710678118654752f));
                Cf[(size_t)m1 * ldC + n]           = v00;
                Cf[(size_t)m1 * ldC + n + 1]       = v01;
                Cf[(size_t)(m1 + 8) * ldC + n]     = v10;
                Cf[(size_t)(m1 + 8) * ldC + n + 1] = v11;
            } else {
                int pa = m1 & 63, pb = (m1 + 8) & 63;
                int ra = (m1 >> 6) * 65 + 1 + pa;
                int rb = ((m1 + 8) >> 6) * 65 + 1 + pb;
                v00 += pos[(1 + pa) * EMBED + n];
                v01 += pos[(1 + pa) * EMBED + n + 1];
                v10 += pos[(1 + pb) * EMBED + n];
                v11 += pos[(1 + pb) * EMBED + n + 1];
                __half2 H0; H0.x = __float2half(v00); H0.y = __float2half(v01);
                __half2 H1; H1.x = __float2half(v10); H1.y = __float2half(v11);
                *(__half2*)(Ch + (size_t)ra * ldC + n) = H0;
                *(__half2*)(Ch + (size_t)rb * ldC + n) = H1;
            }
        }
    }
}

// ---------------------------------------------------------------------------
// K3: per (b,h), 160 threads. Scores 64x64 via fp16 mma (warps 0-3);
// border/max/Z/att0 as job-decomposed half-column partials across all threads.
// ---------------------------------------------------------------------------
#define ASTR 72

__global__ __launch_bounds__(160) void attn_kernel(
    const __half* __restrict__ q16, __half* __restrict__ cp16o)
{
    __shared__ __align__(16) __half sQ[SEQL * ASTR];
    __shared__ float sc[SEQL][68];
    __shared__ float part[2][68];
    __shared__ float pmax[2][68];
    __shared__ float mcolZ[68];     // w0 numerator scratch
    __shared__ float w0s[68];

    const int b = blockIdx.y, h = blockIdx.x;
    const int t = threadIdx.x, lane = t & 31, wid = t >> 5;
    const int gid = lane >> 2, tig = lane & 3;
    const __half* pq = q16 + (size_t)b * SEQL * EMBED + h * HDIM;

    for (int idx = t; idx < SEQL * 8; idx += 160) {
        int row = idx >> 3, c8 = (idx & 7) * 8;
        *(uint4*)(sQ + row * ASTR + c8) = *(const uint4*)(pq + (size_t)row * EMBED + c8);
    }
    __syncthreads();

    // ---- 64x64 score block via MMA on warps 0-3 ----
    if (wid < 4) {
        const uint32_t baseQ = (uint32_t)__cvta_generic_to_shared(&sQ[0]);
        const int m0 = wid * 16;
        const int aoff = (m0 + (lane & 15)) * ASTR + (lane >> 4) * 8;
        const int boffn = ((lane >> 4) << 3) + (lane & 7);
        const int boffk = ((lane >> 3) & 1) * 8;

        float acc[8][4];
        #pragma unroll
        for (int j = 0; j < 8; j++)
            #pragma unroll
            for (int k = 0; k < 4; k++) acc[j][k] = 0.f;

        #pragma unroll
        for (int kc = 0; kc < 4; kc++) {
            const int k0 = kc * 16;
            uint32_t ah[4];
            ldsm4(ah, baseQ + (uint32_t)((aoff + k0) * 2));
            #pragma unroll
            for (int p = 0; p < 4; p++) {
                uint32_t bb[4];
                ldsm4(bb, baseQ + (uint32_t)(((boffn + p * 16) * ASTR + k0 + boffk) * 2));
                mma16816h(acc[2 * p],     ah, bb);
                mma16816h(acc[2 * p + 1], ah, bb + 2);
            }
        }
        #pragma unroll
        for (int nt = 0; nt < 8; nt++) {
            int rr = m0 + gid, cc = nt * 8 + tig * 2;
            sc[rr][cc]         = acc[nt][0] * 0.125f;
            sc[rr][cc + 1]     = acc[nt][1] * 0.125f;
            sc[rr + 8][cc]     = acc[nt][2] * 0.125f;
            sc[rr + 8][cc + 1] = acc[nt][3] * 0.125f;
        }
    }
    // ---- border row 64: 130 jobs (col, k-half), 32 iters each ----
    if (t < 130) {
        const int c = (t < 65) ? t : t - 65;
        const int kh = (t < 65) ? 0 : 1;
        const int kb = kh * 32;
        float a = 0.f;
        #pragma unroll 8
        for (int k = 0; k < 32; k++)
            a += __half2float(sQ[64 * ASTR + kb + k]) * __half2float(sQ[c * ASTR + kb + k]);
        part[kh][c] = a;
    }
    __syncthreads();
    // combine border; write row 64 and (symmetric) column 64
    if (t < SEQL) {
        float v = (part[0][t] + part[1][t]) * 0.125f;
        sc[64][t] = v;
        if (t < 64) sc[t][64] = v;
    }
    __syncthreads();

    // ---- column max: 130 jobs (col, s-half) ----
    if (t < 130) {
        const int c = (t < 65) ? t : t - 65;
        const int s0 = (t < 65) ? 0 : 33;
        const int s1 = (t < 65) ? 33 : 65;
        float m = -1e30f;
        #pragma unroll 4
        for (int s = s0; s < s1; s++) m = fmaxf(m, sc[s][c]);
        pmax[(t < 65) ? 0 : 1][c] = m;
    }
    __syncthreads();

    // ---- Z: 130 jobs, max-combine folded in ----
    if (t < 130) {
        const int c = (t < 65) ? t : t - 65;
        const int s0 = (t < 65) ? 0 : 33;
        const int s1 = (t < 65) ? 33 : 65;
        float m = fmaxf(pmax[0][c], pmax[1][c]);
        float Z = 0.f;
        #pragma unroll 4
        for (int s = s0; s < s1; s++) Z += fexp(sc[s][c] - m);
        part[(t < 65) ? 0 : 1][c] = Z;
    }
    __syncthreads();
    if (t < SEQL) {
        float m = fmaxf(pmax[0][t], pmax[1][t]);
        w0s[t] = fexp(sc[0][t] - m) / (part[0][t] + part[1][t]);
    }
    __syncthreads();

    // ---- att0: 128 jobs (64 cols x 2 s-halves) ----
    if (t < 128) {
        const int c = t & 63;
        const int s0 = (t < 64) ? 0 : 33;
        const int s1 = (t < 64) ? 33 : 65;
        float a = 0.f;
        #pragma unroll 4
        for (int s = s0; s < s1; s++)
            a += w0s[s] * __half2float(sQ[s * ASTR + c]);
        mcolZ[c] = 0.f;   // init combine slot (col c written twice is fine pre-sync? no—)
        part[(t < 64) ? 0 : 1][c] = a;
    }
    __syncthreads();
    if (t < HDIM)
        cp16o[(size_t)b * EMBED + h * HDIM + t] =
            __float2half(part[0][t] + part[1][t]);
}

// logits: one CTA per batch row, one warp per class
__global__ __launch_bounds__(320) void logits_kernel(
    const float* __restrict__ h, const float* __restrict__ w2,
    const float* __restrict__ b2, float* __restrict__ out)
{
    int b = blockIdx.x;
    int lane = threadIdx.x & 31, w = threadIdx.x >> 5;
    const float* hb = h + (size_t)b * HID;
    float a = 0.f;
    for (int k = lane; k < HID; k += 32) a += hb[k] * w2[(size_t)w * HID + k];
    #pragma unroll
    for (int o = 16; o > 0; o >>= 1) a += __shfl_xor_sync(0xffffffffu, a, o);
    if (lane == 0) out[(size_t)b * NCLS + w] = a + b2[w];
}

extern "C" void kernel_launch(void* const* d_in, const int* in_sizes, int n_in,
                              void* d_out, int out_size)
{
    const float* x      = (const float*)d_in[0];
    const float* proj_w = (const float*)d_in[1];
    const float* proj_b = (const float*)d_in[2];
    const float* cls    = (const float*)d_in[3];
    const float* pos    = (const float*)d_in[4];
    const float* wq     = (const float*)d_in[5];
    const float* bq     = (const float*)d_in[6];
    const float* wo     = (const float*)d_in[7];
    const float* bo     = (const float*)d_in[8];
    const float* w1     = (const float*)d_in[9];
    const float* b1     = (const float*)d_in[10];
    const float* w2     = (const float*)d_in[11];
    const float* b2     = (const float*)d_in[12];
    float* out = (float*)d_out;

    __half *p_p, *p_pw, *p_s, *p_wq, *p_wo, *p_w1, *p_q, *p_cp, *p_ct;
    float *p_h;
    cudaGetSymbolAddress((void**)&p_p, g_p16);
    cudaGetSymbolAddress((void**)&p_pw, g_pw16);
    cudaGetSymbolAddress((void**)&p_s, g_s16);
    cudaGetSymbolAddress((void**)&p_wq, g_wq16);
    cudaGetSymbolAddress((void**)&p_wo, g_wo16);
    cudaGetSymbolAddress((void**)&p_w1, g_w116);
    cudaGetSymbolAddress((void**)&p_q, g_q16);
    cudaGetSymbolAddress((void**)&p_cp, g_cp16);
    cudaGetSymbolAddress((void**)&p_ct, g_ct16);
    cudaGetSymbolAddress((void**)&p_h, g_h);

    // 1: fused prep
    prep_kernel<<<PREP_GRID, 256>>>(x, proj_w, cls, pos, wq, wo, w1,
                                    p_p, p_pw, p_s, p_wq, p_wo, p_w1);
    // 2: emb GEMM (mode 2: +pos, row remap)
    mma_gemm_kernel<<<dim3(EMBED / 128, MP / 128), 256>>>(
        p_p, 64, p_pw, 64, proj_b, pos, p_s, nullptr, EMBED, 1, 2);
    // 3: q GEMM
    mma_gemm_kernel<<<dim3(EMBED / 128, MTOT / 128), 256>>>(
        p_s, EMBED, p_wq, EMBED, bq, nullptr, p_q, nullptr, EMBED, 8, 0);
    // 4: attention (ncu capture slot)
    attn_kernel<<<dim3(HEADS, BATCH), 160>>>(p_q, p_cp);
    // 5: wo GEMM
    mma_gemm_kernel<<<dim3(EMBED / 128, BATCH / 128), 256>>>(
        p_cp, EMBED, p_wo, EMBED, bo, nullptr, p_ct, nullptr, EMBED, 8, 0);
    // 6: w1 GEMM + GELU
    mma_gemm_kernel<<<dim3(HID / 128, BATCH / 128), 256>>>(
        p_ct, EMBED, p_w1, EMBED, b1, nullptr, nullptr, p_h, HID, 8, 1);
    // 7: logits
    logits_kernel<<<BATCH, 320>>>(p_h, w2, b2, out);
}

// round 17
// speedup vs baseline: 1.1096x; 1.1096x over previous
#include <cuda_runtime.h>
#include <cuda_fp16.h>
#include <math.h>
#include <stdint.h>

#define EMBED 512
#define HEADS 8
#define HDIM 64
#define SEQL 65
#define NPATCH 64
#define PFEAT 48
#define HID 1024
#define NCLS 10
#define BATCH 2048
#define MTOT (BATCH * SEQL)     // 133120
#define MP (BATCH * NPATCH)     // 131072 (patch GEMM rows)

// global scratch (no allocations allowed)
__device__ __align__(16) __half g_p16[(size_t)MP * 64];
__device__ __align__(16) __half g_pw16[EMBED * 64];
__device__ __align__(16) __half g_s16[(size_t)MTOT * EMBED];
__device__ __align__(16) __half g_wq16[EMBED * EMBED];
__device__ __align__(16) __half g_wo16[EMBED * EMBED];
__device__ __align__(16) __half g_w116[HID * EMBED];
__device__ __align__(16) __half g_q16[(size_t)MTOT * EMBED];
__device__ __align__(16) __half g_cp16[BATCH * EMBED];
__device__ __align__(16) __half g_ct16[BATCH * EMBED];
__device__ __align__(16) float g_h[BATCH * HID];

// ---------------- helpers ----------------
// exp via MUFU ex2 (offloads the fma pipe; ~2^-22 rel err)
__device__ __forceinline__ float fexp(float x) {
    float y = x * 1.4426950408889634f;
    float r;
    asm("ex2.approx.f32 %0, %1;" : "=f"(r) : "f"(y));
    return r;
}
// fp16 x fp16 -> fp32 accum MMA
__device__ __forceinline__ void mma16816h(float* c, const uint32_t* a,
                                          const uint32_t* b) {
    asm volatile(
        "mma.sync.aligned.m16n8k16.row.col.f32.f16.f16.f32 "
        "{%0,%1,%2,%3}, {%4,%5,%6,%7}, {%8,%9}, {%0,%1,%2,%3};"
        : "+f"(c[0]), "+f"(c[1]), "+f"(c[2]), "+f"(c[3])
        : "r"(a[0]), "r"(a[1]), "r"(a[2]), "r"(a[3]), "r"(b[0]), "r"(b[1]));
}
__device__ __forceinline__ void ldsm4(uint32_t* r, uint32_t addr) {
    asm volatile("ldmatrix.sync.aligned.m8n8.x4.shared.b16 {%0,%1,%2,%3}, [%4];"
                 : "=r"(r[0]), "=r"(r[1]), "=r"(r[2]), "=r"(r[3]) : "r"(addr));
}
__device__ __forceinline__ void cp16(uint32_t dst_smem, const void* src) {
    asm volatile("cp.async.ca.shared.global [%0], [%1], 16;"
                 :: "r"(dst_smem), "l"(src));
}
__device__ __forceinline__ void cpcommit() { asm volatile("cp.async.commit_group;"); }
__device__ __forceinline__ void cpwait0()  { asm volatile("cp.async.wait_group 0;"); }

// ---------------------------------------------------------------------------
// K1 "prep": fused patchify (p16, zero-padded K=64) + seq row0 + all weight
// conversions to fp16. Block ranges select the job.
// ---------------------------------------------------------------------------
#define PREP_PATCH 2048
#define PREP_PW    128
#define PREP_WQ    1024
#define PREP_WO    1024
#define PREP_W1    2048
#define PREP_GRID (PREP_PATCH + PREP_PW + PREP_WQ + PREP_WO + PREP_W1)

__global__ __launch_bounds__(256) void prep_kernel(
    const float* __restrict__ x, const float* __restrict__ proj_w,
    const float* __restrict__ cls, const float* __restrict__ pos,
    const float* __restrict__ wq, const float* __restrict__ wo,
    const float* __restrict__ w1,
    __half* __restrict__ p16, __half* __restrict__ pw16,
    __half* __restrict__ s16, __half* __restrict__ wq16,
    __half* __restrict__ wo16, __half* __restrict__ w116)
{
    const int bid = blockIdx.x, t = threadIdx.x;
    if (bid < PREP_PATCH) {
        const int b = bid;
        const float* xb = x + (size_t)b * 3 * 32 * 32;
        __half* pb = p16 + (size_t)b * NPATCH * 64;
        for (int idx = t; idx < NPATCH * PFEAT; idx += 256) {
            int n = idx / PFEAT, f = idx % PFEAT;
            int c = f >> 4, r4 = (f >> 2) & 3, c4 = f & 3;
            int py = n >> 3, px = n & 7;
            pb[n * 64 + f] = __float2half(xb[c * 1024 + (py * 4 + r4) * 32 + (px * 4 + c4)]);
        }
        for (int idx = t; idx < NPATCH * 16; idx += 256) {
            int n = idx >> 4, f = 48 + (idx & 15);
            pb[n * 64 + f] = __float2half(0.f);
        }
        for (int e = t; e < EMBED; e += 256)
            s16[(size_t)b * SEQL * EMBED + e] = __float2half(cls[e] + pos[e]);
        return;
    }
    int r = bid - PREP_PATCH;
    if (r < PREP_PW) {
        int idx = r * 256 + t;
        int row = idx >> 6, col = idx & 63;
        pw16[idx] = __float2half(col < PFEAT ? proj_w[row * PFEAT + col] : 0.f);
        return;
    }
    r -= PREP_PW;
    if (r < PREP_WQ) { int i = r * 256 + t; wq16[i] = __float2half(wq[i]); return; }
    r -= PREP_WQ;
    if (r < PREP_WO) { int i = r * 256 + t; wo16[i] = __float2half(wo[i]); return; }
    r -= PREP_WO;
    { int i = r * 256 + t; w116[i] = __float2half(w1[i]); }
}

// ---------------------------------------------------------------------------
// K2: fp16 MMA GEMM, K-chunk 64, double buffer, ONE barrier per chunk.
// CTA 128x128, 8 warps (4m x 2n), warp tile 32x64.
// mode 0: fp16 out; mode 1: fp32 + exact GELU; mode 2: fp16 out with
// row remap m -> (m/64)*65+1+(m%64) and += pos[(1+m%64)*EMBED + n].
// ---------------------------------------------------------------------------
#define QSTR 72
#define KC 64

__global__ __launch_bounds__(256, 2) void mma_gemm_kernel(
    const __half* __restrict__ A, int ldA,
    const __half* __restrict__ W, int ldW,
    const float* __restrict__ bias, const float* __restrict__ pos,
    __half* __restrict__ Ch, float* __restrict__ Cf,
    int ldC, int nchk, int mode)
{
    __shared__ __align__(16) __half sA[2][128 * QSTR];
    __shared__ __align__(16) __half sW[2][128 * QSTR];

    const int t = threadIdx.x;
    const int wid = t >> 5, lane = t & 31;
    const int gid = lane >> 2, tig = lane & 3;
    const int wm = wid & 3, wn = wid >> 2;
    const int m0 = blockIdx.y * 128, n0 = blockIdx.x * 128;

    float acc[2][8][4];
    #pragma unroll
    for (int i = 0; i < 2; i++)
        #pragma unroll
        for (int j = 0; j < 8; j++)
            #pragma unroll
            for (int k = 0; k < 4; k++) acc[i][j][k] = 0.f;

    const uint32_t stg = 128 * QSTR * 2;
    const uint32_t baseA = (uint32_t)__cvta_generic_to_shared(&sA[0][0]);
    const uint32_t baseW = (uint32_t)__cvta_generic_to_shared(&sW[0][0]);

    const int crow = t >> 3, ccol = (t & 7) * 8;
    auto issue = [&](int c, int s) {
        const uint32_t so = s * stg;
        const size_t ko = (size_t)c * KC + ccol;
        #pragma unroll
        for (int j = 0; j < 4; j++) {
            int row = crow + j * 32;
            uint32_t d = (uint32_t)((row * QSTR + ccol) * 2);
            cp16(baseA + so + d, A + (size_t)(m0 + row) * ldA + ko);
            cp16(baseW + so + d, W + (size_t)(n0 + row) * ldW + ko);
        }
        cpcommit();
    };

    const int aoff = (wm * 32 + (lane & 15)) * QSTR + (lane >> 4) * 8;
    const int boffn = wn * 64 + ((lane >> 4) << 3) + (lane & 7);
    const int boffk = ((lane >> 3) & 1) * 8;

    issue(0, 0);
    for (int c = 0; c < nchk; c++) {
        const int s = c & 1;
        cpwait0();
        __syncthreads();
        if (c + 1 < nchk) issue(c + 1, s ^ 1);
        const uint32_t so = s * stg;
        #pragma unroll
        for (int ks = 0; ks < 4; ks++) {
            const int k0 = ks * 16;
            uint32_t ah[2][4];
            #pragma unroll
            for (int mt = 0; mt < 2; mt++)
                ldsm4(ah[mt], baseA + so + (uint32_t)((aoff + mt * 16 * QSTR + k0) * 2));
            #pragma unroll
            for (int p = 0; p < 4; p++) {
                uint32_t bb[4];
                ldsm4(bb, baseW + so + (uint32_t)(((boffn + p * 16) * QSTR + k0 + boffk) * 2));
                #pragma unroll
                for (int mt = 0; mt < 2; mt++) {
                    mma16816h(acc[mt][2 * p],     ah[mt], bb);
                    mma16816h(acc[mt][2 * p + 1], ah[mt], bb + 2);
                }
            }
        }
    }

    __syncthreads();
    #pragma unroll
    for (int mt = 0; mt < 2; mt++) {
        int m1 = m0 + wm * 32 + mt * 16 + gid;   // rows m1, m1+8
        #pragma unroll
        for (int nt = 0; nt < 8; nt++) {
            int n = n0 + wn * 64 + nt * 8 + tig * 2;
            float b0 = bias[n], b1 = bias[n + 1];
            float v00 = acc[mt][nt][0] + b0, v01 = acc[mt][nt][1] + b1;
            float v10 = acc[mt][nt][2] + b0, v11 = acc[mt][nt][3] + b1;
            if (mode == 0) {
                __half2 H0; H0.x = __float2half(v00); H0.y = __float2half(v01);
                __half2 H1; H1.x = __float2half(v10); H1.y = __float2half(v11);
                *(__half2*)(Ch + (size_t)m1 * ldC + n)       = H0;
                *(__half2*)(Ch + (size_t)(m1 + 8) * ldC + n) = H1;
            } else if (mode == 1) {
                v00 = 0.5f * v00 * (1.f + erff(v00 * 0.70710678118654752f));
                v01 = 0.5f * v01 * (1.f + erff(v01 * 0.70710678118654752f));
                v10 = 0.5f * v10 * (1.f + erff(v10 * 0.70710678118654752f));
                v11 = 0.5f * v11 * (1.f + erff(v11 * 0.70710678118654752f));
                Cf[(size_t)m1 * ldC + n]           = v00;
                Cf[(size_t)m1 * ldC + n + 1]       = v01;
                Cf[(size_t)(m1 + 8) * ldC + n]     = v10;
                Cf[(size_t)(m1 + 8) * ldC + n + 1] = v11;
            } else {
                int pa = m1 & 63, pb = (m1 + 8) & 63;
                int ra = (m1 >> 6) * 65 + 1 + pa;
                int rb = ((m1 + 8) >> 6) * 65 + 1 + pb;
                v00 += pos[(1 + pa) * EMBED + n];
                v01 += pos[(1 + pa) * EMBED + n + 1];
                v10 += pos[(1 + pb) * EMBED + n];
                v11 += pos[(1 + pb) * EMBED + n + 1];
                __half2 H0; H0.x = __float2half(v00); H0.y = __float2half(v01);
                __half2 H1; H1.x = __float2half(v10); H1.y = __float2half(v11);
                *(__half2*)(Ch + (size_t)ra * ldC + n) = H0;
                *(__half2*)(Ch + (size_t)rb * ldC + n) = H1;
            }
        }
    }
}

// ---------------------------------------------------------------------------
// K3: per (b,h), 128 threads. Scores 64x64 via fp16 mma; softmax stats from
// the symmetric rows held in MMA fragments. Border exp added ONCE after the
// tig-group reduction (R16 fix); row-64 softmax includes diagonal (R15 fix).
// ---------------------------------------------------------------------------
#define ASTR 72

__global__ __launch_bounds__(128) void attn_kernel(
    const __half* __restrict__ q16, __half* __restrict__ cp16o)
{
    __shared__ __align__(16) __half sQ[SEQL * ASTR];
    __shared__ float bcol[68];   // scaled border: bcol[t] = (q64 . qt)/8
    __shared__ float w0s[68];

    const int b = blockIdx.y, h = blockIdx.x;
    const int t = threadIdx.x, lane = t & 31, wid = t >> 5;
    const int gid = lane >> 2, tig = lane & 3;
    const __half* pq = q16 + (size_t)b * SEQL * EMBED + h * HDIM;

    for (int idx = t; idx < SEQL * 8; idx += 128) {
        int row = idx >> 3, c8 = (idx & 7) * 8;
        *(uint4*)(sQ + row * ASTR + c8) = *(const uint4*)(pq + (size_t)row * EMBED + c8);
    }
    __syncthreads();

    // ---- 64x64 score block via MMA (row index = first softmax index) ----
    const uint32_t baseQ = (uint32_t)__cvta_generic_to_shared(&sQ[0]);
    const int m0 = wid * 16;
    const int aoff = (m0 + (lane & 15)) * ASTR + (lane >> 4) * 8;
    const int boffn = ((lane >> 4) << 3) + (lane & 7);
    const int boffk = ((lane >> 3) & 1) * 8;

    float acc[8][4];
    #pragma unroll
    for (int j = 0; j < 8; j++)
        #pragma unroll
        for (int k = 0; k < 4; k++) acc[j][k] = 0.f;

    #pragma unroll
    for (int kc = 0; kc < 4; kc++) {
        const int k0 = kc * 16;
        uint32_t ah[4];
        ldsm4(ah, baseQ + (uint32_t)((aoff + k0) * 2));
        #pragma unroll
        for (int p = 0; p < 4; p++) {
            uint32_t bb[4];
            ldsm4(bb, baseQ + (uint32_t)(((boffn + p * 16) * ASTR + k0 + boffk) * 2));
            mma16816h(acc[2 * p],     ah, bb);
            mma16816h(acc[2 * p + 1], ah, bb + 2);
        }
    }
    // scale all fragments once
    #pragma unroll
    for (int j = 0; j < 8; j++)
        #pragma unroll
        for (int k = 0; k < 4; k++) acc[j][k] *= 0.125f;

    // ---- border row 64: threads 63..127 -> cols 0..64 (scaled) ----
    if (t >= 63) {
        int tt = t - 63;
        float a0 = 0.f, a1 = 0.f;
        #pragma unroll 4
        for (int k = 0; k < HDIM; k += 2) {
            a0 += __half2float(sQ[64 * ASTR + k]) * __half2float(sQ[tt * ASTR + k]);
            a1 += __half2float(sQ[64 * ASTR + k + 1]) * __half2float(sQ[tt * ASTR + k + 1]);
        }
        bcol[tt] = (a0 + a1) * 0.125f;
    }
    __syncthreads();

    // ---- softmax stats from fragment rows (symmetry: col t == row t) ----
    {
        const int rA = m0 + gid, rB = rA + 8;
        float bA = bcol[rA], bB = bcol[rB];
        float mA = bA, mB = bB;     // fmax idempotent: safe on all 4 lanes
        #pragma unroll
        for (int nt = 0; nt < 8; nt++) {
            mA = fmaxf(mA, fmaxf(acc[nt][0], acc[nt][1]));
            mB = fmaxf(mB, fmaxf(acc[nt][2], acc[nt][3]));
        }
        mA = fmaxf(mA, __shfl_xor_sync(0xffffffffu, mA, 1));
        mA = fmaxf(mA, __shfl_xor_sync(0xffffffffu, mA, 2));
        mB = fmaxf(mB, __shfl_xor_sync(0xffffffffu, mB, 1));
        mB = fmaxf(mB, __shfl_xor_sync(0xffffffffu, mB, 2));

        float zA = 0.f, zB = 0.f;   // MMA columns only; border added post-reduce
        float n0A = 0.f, n0B = 0.f;
        #pragma unroll
        for (int nt = 0; nt < 8; nt++) {
            float e0 = fexp(acc[nt][0] - mA), e1 = fexp(acc[nt][1] - mA);
            float e2 = fexp(acc[nt][2] - mB), e3 = fexp(acc[nt][3] - mB);
            zA += e0 + e1; zB += e2 + e3;
            if (nt == 0) { n0A = e0; n0B = e2; }   // col s=0 lives at nt=0,tig=0
        }
        zA += __shfl_xor_sync(0xffffffffu, zA, 1);
        zA += __shfl_xor_sync(0xffffffffu, zA, 2);
        zB += __shfl_xor_sync(0xffffffffu, zB, 1);
        zB += __shfl_xor_sync(0xffffffffu, zB, 2);
        zA += fexp(bA - mA);        // border term exactly once
        zB += fexp(bB - mB);
        if (tig == 0) {
            w0s[rA] = n0A / zA;
            w0s[rB] = n0B / zB;
        }
    }
    // ---- row 64 softmax: warp 0 shuffle reduction over bcol[0..64] ----
    if (wid == 0) {
        float v0 = bcol[lane];          // cols 0..31
        float v1 = bcol[lane + 32];     // cols 32..63
        float v2 = bcol[64];            // diagonal term (uniform on all lanes)
        float m = fmaxf(fmaxf(v0, v1), v2);
        #pragma unroll
        for (int o = 16; o > 0; o >>= 1)
            m = fmaxf(m, __shfl_xor_sync(0xffffffffu, m, o));
        float z = fexp(v0 - m) + fexp(v1 - m);
        #pragma unroll
        for (int o = 16; o > 0; o >>= 1)
            z += __shfl_xor_sync(0xffffffffu, z, o);
        if (lane == 0)
            w0s[64] = fexp(bcol[0] - m) / (z + fexp(v2 - m));
    }
    __syncthreads();

    // ---- att0: 64 threads, 65-term weighted sum (2-way ILP) ----
    if (t < HDIM) {
        float a0 = 0.f, a1 = 0.f;
        for (int s = 0; s < 64; s += 2) {
            a0 += w0s[s] * __half2float(sQ[s * ASTR + t]);
            a1 += w0s[s + 1] * __half2float(sQ[(s + 1) * ASTR + t]);
        }
        float a = a0 + a1 + w0s[64] * __half2float(sQ[64 * ASTR + t]);
        cp16o[(size_t)b * EMBED + h * HDIM + t] = __float2half(a);
    }
}

// logits: one CTA per batch row, one warp per class
__global__ __launch_bounds__(320) void logits_kernel(
    const float* __restrict__ h, const float* __restrict__ w2,
    const float* __restrict__ b2, float* __restrict__ out)
{
    int b = blockIdx.x;
    int lane = threadIdx.x & 31, w = threadIdx.x >> 5;
    const float* hb = h + (size_t)b * HID;
    float a = 0.f;
    for (int k = lane; k < HID; k += 32) a += hb[k] * w2[(size_t)w * HID + k];
    #pragma unroll
    for (int o = 16; o > 0; o >>= 1) a += __shfl_xor_sync(0xffffffffu, a, o);
    if (lane == 0) out[(size_t)b * NCLS + w] = a + b2[w];
}

extern "C" void kernel_launch(void* const* d_in, const int* in_sizes, int n_in,
                              void* d_out, int out_size)
{
    const float* x      = (const float*)d_in[0];
    const float* proj_w = (const float*)d_in[1];
    const float* proj_b = (const float*)d_in[2];
    const float* cls    = (const float*)d_in[3];
    const float* pos    = (const float*)d_in[4];
    const float* wq     = (const float*)d_in[5];
    const float* bq     = (const float*)d_in[6];
    const float* wo     = (const float*)d_in[7];
    const float* bo     = (const float*)d_in[8];
    const float* w1     = (const float*)d_in[9];
    const float* b1     = (const float*)d_in[10];
    const float* w2     = (const float*)d_in[11];
    const float* b2     = (const float*)d_in[12];
    float* out = (float*)d_out;

    __half *p_p, *p_pw, *p_s, *p_wq, *p_wo, *p_w1, *p_q, *p_cp, *p_ct;
    float *p_h;
    cudaGetSymbolAddress((void**)&p_p, g_p16);
    cudaGetSymbolAddress((void**)&p_pw, g_pw16);
    cudaGetSymbolAddress((void**)&p_s, g_s16);
    cudaGetSymbolAddress((void**)&p_wq, g_wq16);
    cudaGetSymbolAddress((void**)&p_wo, g_wo16);
    cudaGetSymbolAddress((void**)&p_w1, g_w116);
    cudaGetSymbolAddress((void**)&p_q, g_q16);
    cudaGetSymbolAddress((void**)&p_cp, g_cp16);
    cudaGetSymbolAddress((void**)&p_ct, g_ct16);
    cudaGetSymbolAddress((void**)&p_h, g_h);

    // 1: fused prep
    prep_kernel<<<PREP_GRID, 256>>>(x, proj_w, cls, pos, wq, wo, w1,
                                    p_p, p_pw, p_s, p_wq, p_wo, p_w1);
    // 2: emb GEMM (mode 2: +pos, row remap)
    mma_gemm_kernel<<<dim3(EMBED / 128, MP / 128), 256>>>(
        p_p, 64, p_pw, 64, proj_b, pos, p_s, nullptr, EMBED, 1, 2);
    // 3: q GEMM
    mma_gemm_kernel<<<dim3(EMBED / 128, MTOT / 128), 256>>>(
        p_s, EMBED, p_wq, EMBED, bq, nullptr, p_q, nullptr, EMBED, 8, 0);
    // 4: attention (ncu capture slot)
    attn_kernel<<<dim3(HEADS, BATCH), 128>>>(p_q, p_cp);
    // 5: wo GEMM
    mma_gemm_kernel<<<dim3(EMBED / 128, BATCH / 128), 256>>>(
        p_cp, EMBED, p_wo, EMBED, bo, nullptr, p_ct, nullptr, EMBED, 8, 0);
    // 6: w1 GEMM + GELU
    mma_gemm_kernel<<<dim3(HID / 128, BATCH / 128), 256>>>(
        p_ct, EMBED, p_w1, EMBED, b1, nullptr, nullptr, p_h, HID, 8, 1);
    // 7: logits
    logits_kernel<<<BATCH, 320>>>(p_h, w2, b2, out);
}